// round 15
// baseline (speedup 1.0000x reference)
#include <cuda_runtime.h>
#include <stdint.h>

#define EPSF 1e-6f

#define NB 32
#define NS 8
#define HW 65536
#define NACC 66
// per-batch accumulator layout:
//   [0..48]  fg inter[p*7+g]  (pred slot p+1, gt slot g+1)
//   [49..56] sum_pred[s], [57..64] sum_gt[s], [65] bg inter

#define C 9              // chunks (blocks) per batch -> grid 288 <= 296 residency
#define TPB 256
#define TILE_PX 512
#define ROW_F2 (TILE_PX / 2)              // 256 float2 per row
#define STAGE_FLOATS (16 * TILE_PX)       // 8192 floats = 32KB per stage
#define NSTAGE 3
#define DYN_SMEM (NSTAGE * STAGE_FLOATS * 4)

__device__ float g_part[NB][C][NACC];
__device__ float g_bg[NB];
__device__ float g_fg[NB];
__device__ int   g_n[NB];
__device__ int   cnt_batch[NB];   // zero-init; restored by kernel each run
__device__ int   cnt_global;

__device__ __forceinline__ float warp_sum(float v) {
    #pragma unroll
    for (int off = 16; off > 0; off >>= 1)
        v += __shfl_down_sync(0xffffffffu, v, off);
    return v;
}

__device__ __forceinline__ void cp_async16(uint32_t dst_smem, const void* src) {
    asm volatile("cp.async.cg.shared.global [%0], [%1], 16;"
                 :: "r"(dst_smem), "l"(src));
}
__device__ __forceinline__ void cp_commit() {
    asm volatile("cp.async.commit_group;");
}
__device__ __forceinline__ void cp_wait2() {
    asm volatile("cp.async.wait_group 2;");
}

struct Acc {
    float inter[49];
    float sp[8], sg[8];
    float bgi;
};

__device__ __forceinline__ void consume(Acc& a, const float2 (&p)[8],
                                        const float2 (&g)[8]) {
    #pragma unroll
    for (int s = 0; s < 8; s++) a.sp[s] += p[s].x + p[s].y;
    #pragma unroll
    for (int s = 0; s < 8; s++) a.sg[s] += g[s].x + g[s].y;
    a.bgi = fmaf(p[0].x, g[0].x, a.bgi);
    a.bgi = fmaf(p[0].y, g[0].y, a.bgi);
    #pragma unroll
    for (int i = 1; i < 8; i++)
        #pragma unroll
        for (int j = 1; j < 8; j++) {
            float acc = a.inter[(i - 1) * 7 + (j - 1)];
            acc = fmaf(p[i].x, g[j].x, acc);
            acc = fmaf(p[i].y, g[j].y, acc);
            a.inter[(i - 1) * 7 + (j - 1)] = acc;
        }
}

// Stage one tile (16 rows x TILE_PX px) into smem buffer `buf`.
// 2048 16B-chunks, 8 per thread. Chunks past px_hi are zero-filled.
__device__ __forceinline__ void issue_stage(float* sdyn, int buf,
                                            const float* __restrict__ pb,
                                            const float* __restrict__ gb,
                                            int px_lo, int px_hi) {
    float* sb = sdyn + buf * STAGE_FLOATS;
    uint32_t sbase = (uint32_t)__cvta_generic_to_shared(sb);
    #pragma unroll
    for (int k = 0; k < 8; k++) {
        int c = threadIdx.x + (k << 8);      // 0..2047
        int row = c >> 7;                    // 0..15
        int off = c & 127;                   // 16B chunk within row
        int px = px_lo + (off << 2);
        uint32_t dst = sbase + (uint32_t)(row * TILE_PX + (off << 2)) * 4u;
        if (px < px_hi) {
            const float* src = (row < 8 ? pb + row * HW : gb + (row - 8) * HW) + px;
            cp_async16(dst, src);
        } else {
            float4 z = make_float4(0.f, 0.f, 0.f, 0.f);
            *reinterpret_cast<float4*>(sb + row * TILE_PX + (off << 2)) = z;
        }
    }
}

__global__ __launch_bounds__(TPB, 2)
void fused_kernel(const float* __restrict__ pred, const float* __restrict__ gt,
                  const int* __restrict__ num_objects, float* __restrict__ out) {
    extern __shared__ float sdyn[];

    const int b = blockIdx.x / C;
    const int chunk = blockIdx.x % C;
    // 4-px-aligned ranges: every 16B chunk is fully in-range or fully out
    const int lo = (int)(((long long)chunk * HW) / C) & ~3;
    const int hi = (chunk == C - 1) ? HW
                   : ((int)(((long long)(chunk + 1) * HW) / C) & ~3);

    const float* __restrict__ pb = pred + (size_t)b * NS * HW;
    const float* __restrict__ gb = gt   + (size_t)b * NS * HW;

    const int tiles = (hi - lo + TILE_PX - 1) / TILE_PX;

    // prologue: fill the pipeline (uniform group count via empty commits)
    #pragma unroll
    for (int s = 0; s < NSTAGE; s++) {
        if (s < tiles) issue_stage(sdyn, s, pb, gb, lo + s * TILE_PX, hi);
        cp_commit();
    }

    Acc a;
    #pragma unroll
    for (int k = 0; k < 49; k++) a.inter[k] = 0.0f;
    #pragma unroll
    for (int s = 0; s < 8; s++) { a.sp[s] = 0.0f; a.sg[s] = 0.0f; }
    a.bgi = 0.0f;

    for (int t = 0; t < tiles; t++) {
        cp_wait2();            // group t complete (<=2 newer pending)
        __syncthreads();       // make all threads' copies visible

        const int buf = t % NSTAGE;
        const float2* base = (const float2*)(sdyn + buf * STAGE_FLOATS);
        float2 p[8], g[8];
        #pragma unroll
        for (int s = 0; s < 8; s++) p[s] = base[s * ROW_F2 + threadIdx.x];
        #pragma unroll
        for (int s = 0; s < 8; s++) g[s] = base[(8 + s) * ROW_F2 + threadIdx.x];
        consume(a, p, g);

        __syncthreads();       // all reads done before refilling this buffer
        const int nt = t + NSTAGE;
        if (nt < tiles) issue_stage(sdyn, buf, pb, gb, lo + nt * TILE_PX, hi);
        cp_commit();           // empty group if past the end (keeps count uniform)
    }

    // ---- block reduction -> g_part[b][chunk][*] ----
    __shared__ float wsum[TPB / 32][NACC];
    __shared__ float a_sm[NACC];
    __shared__ float dice_sm[49];
    __shared__ float dp_sm[128];
    __shared__ int   flag_sm;

    const int wid = threadIdx.x >> 5;
    const int lane = threadIdx.x & 31;

    #pragma unroll
    for (int k = 0; k < 49; k++) {
        float v = warp_sum(a.inter[k]);
        if (lane == 0) wsum[wid][k] = v;
    }
    #pragma unroll
    for (int s = 0; s < 8; s++) {
        float v = warp_sum(a.sp[s]);
        if (lane == 0) wsum[wid][49 + s] = v;
    }
    #pragma unroll
    for (int s = 0; s < 8; s++) {
        float v = warp_sum(a.sg[s]);
        if (lane == 0) wsum[wid][57 + s] = v;
    }
    {
        float v = warp_sum(a.bgi);
        if (lane == 0) wsum[wid][65] = v;
    }
    __syncthreads();
    if (threadIdx.x < NACC) {
        float v = 0.0f;
        #pragma unroll
        for (int w = 0; w < TPB / 32; w++) v += wsum[w][threadIdx.x];
        g_part[b][chunk][threadIdx.x] = v;
    }
    __threadfence();
    __syncthreads();

    // ---- last block of this batch runs the batch finalize ----
    if (threadIdx.x == 0) {
        int old = atomicAdd(&cnt_batch[b], 1);
        flag_sm = (old == C - 1) ? 1 : 0;
    }
    __syncthreads();
    if (!flag_sm) return;
    __threadfence();   // acquire: see all chunks' g_part writes

    if (wid == 0) {
        int n = num_objects[b];
        if (n > 7) n = 7;
        if (n < 0) n = 0;

        // sum partials over chunks
        for (int k = lane; k < NACC; k += 32) {
            float v = 0.0f;
            #pragma unroll
            for (int c = 0; c < C; c++) v += g_part[b][c][k];
            a_sm[k] = v;
        }
        __syncwarp();

        // dice matrix (pred p, gt g) — all 49 entries
        for (int idx = lane; idx < 49; idx += 32) {
            int p = idx / 7, g = idx % 7;
            dice_sm[idx] = (2.0f * a_sm[idx] + EPSF) /
                           (a_sm[50 + p] + a_sm[58 + g] + EPSF);
        }
        __syncwarp();

        // subset DP over pred-slot sets (exact optimal-assignment sum)
        #pragma unroll
        for (int q = 0; q < 4; q++) {
            int S = lane + 32 * q;
            dp_sm[S] = (S == 0) ? 0.0f : -1e30f;
        }
        __syncwarp();
        for (int k = 1; k <= n; k++) {
            float newv[4];
            #pragma unroll
            for (int q = 0; q < 4; q++) {
                int S = lane + 32 * q;
                float best = -1e30f;
                if (__popc(S) == k) {
                    #pragma unroll
                    for (int j = 0; j < 7; j++) {
                        if (S & (1 << j)) {
                            float cand = dp_sm[S & ~(1 << j)] + dice_sm[j * 7 + (k - 1)];
                            best = fmaxf(best, cand);
                        }
                    }
                }
                newv[q] = best;
            }
            __syncwarp();
            #pragma unroll
            for (int q = 0; q < 4; q++) {
                int S = lane + 32 * q;
                if (__popc(S) == k) dp_sm[S] = newv[q];
            }
            __syncwarp();
        }

        float best = -1e30f;
        #pragma unroll
        for (int q = 0; q < 4; q++) {
            int S = lane + 32 * q;
            if (__popc(S) == n) best = fmaxf(best, dp_sm[S]);
        }
        #pragma unroll
        for (int off = 16; off > 0; off >>= 1)
            best = fmaxf(best, __shfl_down_sync(0xffffffffu, best, off));

        if (lane == 0) {
            g_bg[b] = 1.0f - (2.0f * a_sm[65] + EPSF) /
                             (a_sm[49] + a_sm[57] + EPSF);
            g_fg[b] = (n > 0) ? ((float)n - best) : 0.0f;
            g_n[b]  = n;
            __threadfence();

            // ---- global finalize by the last batch finalizer ----
            int gold = atomicAdd(&cnt_global, 1);
            if (gold == NB - 1) {
                __threadfence();
                float bg = 0.0f, fg = 0.0f;
                int cn = 0;
                #pragma unroll
                for (int bb = 0; bb < NB; bb++) {
                    bg += g_bg[bb];
                    fg += g_fg[bb];
                    cn += g_n[bb];
                }
                float bg_loss = bg / (float)NB;
                float fg_loss = (cn > 0) ? (fg / (float)cn) : 0.0f;
                out[0] = bg_loss + fg_loss;
                // reset counters for the next graph replay
                #pragma unroll
                for (int bb = 0; bb < NB; bb++) cnt_batch[bb] = 0;
                cnt_global = 0;
                __threadfence();
            }
        }
    }
}

extern "C" void kernel_launch(void* const* d_in, const int* in_sizes, int n_in,
                              void* d_out, int out_size) {
    const float* pred = (const float*)d_in[0];
    const float* gt   = (const float*)d_in[1];
    const int*   nobj = (const int*)d_in[2];
    float* out = (float*)d_out;

    cudaFuncSetAttribute(fused_kernel,
                         cudaFuncAttributeMaxDynamicSharedMemorySize, DYN_SMEM);
    fused_kernel<<<NB * C, TPB, DYN_SMEM>>>(pred, gt, nobj, out);
}

// round 16
// speedup vs baseline: 1.0539x; 1.0539x over previous
#include <cuda_runtime.h>
#include <stdint.h>

#define EPSF 1e-6f

#define NB 32
#define NS 8
#define HW 65536
#define HW2 (HW / 2)
#define NACC 66
// per-batch accumulator layout:
//   [0..48]  fg inter[p*7+g]  (pred slot p+1, gt slot g+1)
//   [49..56] sum_pred[s], [57..64] sum_gt[s], [65] bg inter

#define NCHUNK 13
#define TPB 128

__device__ float g_part[NB][NCHUNK][NACC];
__device__ float g_bg[NB];
__device__ float g_fg[NB];
__device__ int   g_n[NB];
__device__ int   cnt_batch[NB];   // zero-init; restored by kernel each run
__device__ int   cnt_global;

__device__ __forceinline__ float warp_sum(float v) {
    #pragma unroll
    for (int off = 16; off > 0; off >>= 1)
        v += __shfl_down_sync(0xffffffffu, v, off);
    return v;
}

// packed f32x2 FMA: d.lo = a.lo*b.lo + c.lo ; d.hi = a.hi*b.hi + c.hi
__device__ __forceinline__ unsigned long long ffma2(unsigned long long a,
                                                    unsigned long long b,
                                                    unsigned long long c) {
    unsigned long long d;
    asm("fma.rn.f32x2 %0, %1, %2, %3;" : "=l"(d) : "l"(a), "l"(b), "l"(c));
    return d;
}

__device__ __forceinline__ float2 unpack2(unsigned long long v) {
    float2 f;
    asm("mov.b64 {%0, %1}, %2;" : "=f"(f.x), "=f"(f.y) : "l"(v));
    return f;
}

__global__ __launch_bounds__(TPB, 3)
void fused_kernel(const float* __restrict__ pred, const float* __restrict__ gt,
                  const int* __restrict__ num_objects, float* __restrict__ out) {
    const int b = blockIdx.x / NCHUNK;
    const int chunk = blockIdx.x % NCHUNK;
    // range-based chunking in float2 units (no divisibility requirement)
    const int lo = (int)(((long long)chunk * HW2) / NCHUNK);
    const int hi = (int)(((long long)(chunk + 1) * HW2) / NCHUNK);

    const unsigned long long* __restrict__ pb =
        (const unsigned long long*)(pred + (size_t)b * NS * HW);
    const unsigned long long* __restrict__ gb =
        (const unsigned long long*)(gt + (size_t)b * NS * HW);

    unsigned long long inter2[49];   // packed f32x2 accumulators
    unsigned long long bg2 = 0ull;
    float sp[8], sg[8];
    #pragma unroll
    for (int k = 0; k < 49; k++) inter2[k] = 0ull;
    #pragma unroll
    for (int s = 0; s < 8; s++) { sp[s] = 0.0f; sg[s] = 0.0f; }

    for (int pix = lo + threadIdx.x; pix < hi; pix += TPB) {
        unsigned long long p[8], g[8];
        #pragma unroll
        for (int s = 0; s < 8; s++) p[s] = __ldcs(&pb[s * HW2 + pix]);
        #pragma unroll
        for (int s = 0; s < 8; s++) g[s] = __ldcs(&gb[s * HW2 + pix]);

        #pragma unroll
        for (int s = 0; s < 8; s++) {
            float2 t = unpack2(p[s]);
            sp[s] += t.x + t.y;
        }
        #pragma unroll
        for (int s = 0; s < 8; s++) {
            float2 t = unpack2(g[s]);
            sg[s] += t.x + t.y;
        }
        bg2 = ffma2(p[0], g[0], bg2);
        #pragma unroll
        for (int i = 1; i < 8; i++)
            #pragma unroll
            for (int j = 1; j < 8; j++)
                inter2[(i - 1) * 7 + (j - 1)] =
                    ffma2(p[i], g[j], inter2[(i - 1) * 7 + (j - 1)]);
    }

    // ---- block reduction -> g_part[b][chunk][*] ----
    __shared__ float wsum[TPB / 32][NACC];
    __shared__ float a_sm[NACC];
    __shared__ float dice_sm[49];
    __shared__ float dp_sm[128];
    __shared__ int   flag_sm;

    const int wid = threadIdx.x >> 5;
    const int lane = threadIdx.x & 31;

    #pragma unroll
    for (int k = 0; k < 49; k++) {
        float2 t = unpack2(inter2[k]);
        float v = warp_sum(t.x + t.y);
        if (lane == 0) wsum[wid][k] = v;
    }
    #pragma unroll
    for (int s = 0; s < 8; s++) {
        float v = warp_sum(sp[s]);
        if (lane == 0) wsum[wid][49 + s] = v;
    }
    #pragma unroll
    for (int s = 0; s < 8; s++) {
        float v = warp_sum(sg[s]);
        if (lane == 0) wsum[wid][57 + s] = v;
    }
    {
        float2 t = unpack2(bg2);
        float v = warp_sum(t.x + t.y);
        if (lane == 0) wsum[wid][65] = v;
    }
    __syncthreads();
    if (threadIdx.x < NACC) {
        float v = 0.0f;
        #pragma unroll
        for (int w = 0; w < TPB / 32; w++) v += wsum[w][threadIdx.x];
        g_part[b][chunk][threadIdx.x] = v;
    }
    __threadfence();
    __syncthreads();

    // ---- last block of this batch runs the batch finalize ----
    if (threadIdx.x == 0) {
        int old = atomicAdd(&cnt_batch[b], 1);
        flag_sm = (old == NCHUNK - 1) ? 1 : 0;
    }
    __syncthreads();
    if (!flag_sm) return;
    __threadfence();   // acquire: see all chunks' g_part writes

    if (wid == 0) {
        int n = num_objects[b];
        if (n > 7) n = 7;
        if (n < 0) n = 0;

        // sum partials over chunks
        for (int k = lane; k < NACC; k += 32) {
            float v = 0.0f;
            #pragma unroll
            for (int c = 0; c < NCHUNK; c++) v += g_part[b][c][k];
            a_sm[k] = v;
        }
        __syncwarp();

        // dice matrix (pred p, gt g) — all 49 entries
        for (int idx = lane; idx < 49; idx += 32) {
            int p = idx / 7, g = idx % 7;
            dice_sm[idx] = (2.0f * a_sm[idx] + EPSF) /
                           (a_sm[50 + p] + a_sm[58 + g] + EPSF);
        }
        __syncwarp();

        // subset DP over pred-slot sets (exact optimal-assignment sum)
        #pragma unroll
        for (int q = 0; q < 4; q++) {
            int S = lane + 32 * q;
            dp_sm[S] = (S == 0) ? 0.0f : -1e30f;
        }
        __syncwarp();
        for (int k = 1; k <= n; k++) {
            float newv[4];
            #pragma unroll
            for (int q = 0; q < 4; q++) {
                int S = lane + 32 * q;
                float best = -1e30f;
                if (__popc(S) == k) {
                    #pragma unroll
                    for (int j = 0; j < 7; j++) {
                        if (S & (1 << j)) {
                            float cand = dp_sm[S & ~(1 << j)] + dice_sm[j * 7 + (k - 1)];
                            best = fmaxf(best, cand);
                        }
                    }
                }
                newv[q] = best;
            }
            __syncwarp();
            #pragma unroll
            for (int q = 0; q < 4; q++) {
                int S = lane + 32 * q;
                if (__popc(S) == k) dp_sm[S] = newv[q];
            }
            __syncwarp();
        }

        float best = -1e30f;
        #pragma unroll
        for (int q = 0; q < 4; q++) {
            int S = lane + 32 * q;
            if (__popc(S) == n) best = fmaxf(best, dp_sm[S]);
        }
        #pragma unroll
        for (int off = 16; off > 0; off >>= 1)
            best = fmaxf(best, __shfl_down_sync(0xffffffffu, best, off));

        if (lane == 0) {
            g_bg[b] = 1.0f - (2.0f * a_sm[65] + EPSF) /
                             (a_sm[49] + a_sm[57] + EPSF);
            g_fg[b] = (n > 0) ? ((float)n - best) : 0.0f;
            g_n[b]  = n;
            __threadfence();

            // ---- global finalize by the last batch finalizer ----
            int gold = atomicAdd(&cnt_global, 1);
            if (gold == NB - 1) {
                __threadfence();
                float bg = 0.0f, fg = 0.0f;
                int cn = 0;
                #pragma unroll
                for (int bb = 0; bb < NB; bb++) {
                    bg += g_bg[bb];
                    fg += g_fg[bb];
                    cn += g_n[bb];
                }
                float bg_loss = bg / (float)NB;
                float fg_loss = (cn > 0) ? (fg / (float)cn) : 0.0f;
                out[0] = bg_loss + fg_loss;
                // reset counters for the next graph replay
                #pragma unroll
                for (int bb = 0; bb < NB; bb++) cnt_batch[bb] = 0;
                cnt_global = 0;
                __threadfence();
            }
        }
    }
}

extern "C" void kernel_launch(void* const* d_in, const int* in_sizes, int n_in,
                              void* d_out, int out_size) {
    const float* pred = (const float*)d_in[0];
    const float* gt   = (const float*)d_in[1];
    const int*   nobj = (const int*)d_in[2];
    float* out = (float*)d_out;

    fused_kernel<<<NB * NCHUNK, TPB>>>(pred, gt, nobj, out);
}

// round 17
// speedup vs baseline: 1.1050x; 1.0485x over previous
#include <cuda_runtime.h>
#include <stdint.h>

#define EPSF 1e-6f

#define NB 32
#define NS 8
#define HW 65536
#define NACC 66
// per-batch accumulator layout:
//   [0..48]  fg inter[p*7+g], [49..56] sum_pred[s], [57..64] sum_gt[s], [65] bg inter

#define TPB 128
#define TILE_PX 512
#define ROW_BYTES (TILE_PX * 4)            // 2048
#define STAGE_BYTES (16 * ROW_BYTES)       // 32768
#define STAGE_FLOATS (16 * TILE_PX)        // 8192
#define NSTAGE 2
#define DYN_SMEM (NSTAGE * STAGE_BYTES)
#define TILES_PER_BATCH (HW / TILE_PX)     // 128
#define MAXCHUNK 14
// grid = 444 = 3*148 exactly: batches 0..27 -> 14 chunks, 28..31 -> 13 chunks
#define GRID_BLOCKS 444

__device__ float g_part[NB][MAXCHUNK][NACC];
__device__ float g_bg[NB];
__device__ float g_fg[NB];
__device__ int   g_n[NB];
__device__ int   cnt_batch[NB];   // zero-init; restored by kernel each run
__device__ int   cnt_global;

__device__ __forceinline__ float warp_sum(float v) {
    #pragma unroll
    for (int off = 16; off > 0; off >>= 1)
        v += __shfl_down_sync(0xffffffffu, v, off);
    return v;
}

typedef unsigned long long u64;

__device__ __forceinline__ u64 ffma2(u64 a, u64 b, u64 c) {
    u64 d;
    asm("fma.rn.f32x2 %0, %1, %2, %3;" : "=l"(d) : "l"(a), "l"(b), "l"(c));
    return d;
}
__device__ __forceinline__ u64 add2(u64 a, u64 b) {
    u64 d;
    asm("add.rn.f32x2 %0, %1, %2;" : "=l"(d) : "l"(a), "l"(b));
    return d;
}
__device__ __forceinline__ float2 unpack2(u64 v) {
    float2 f;
    asm("mov.b64 {%0, %1}, %2;" : "=f"(f.x), "=f"(f.y) : "l"(v));
    return f;
}

__device__ __forceinline__ void mbar_init(uint32_t mbar, uint32_t count) {
    asm volatile("mbarrier.init.shared.b64 [%0], %1;" :: "r"(mbar), "r"(count) : "memory");
}
__device__ __forceinline__ void mbar_expect_tx(uint32_t mbar, uint32_t bytes) {
    asm volatile("mbarrier.arrive.expect_tx.shared.b64 _, [%0], %1;"
                 :: "r"(mbar), "r"(bytes) : "memory");
}
__device__ __forceinline__ void mbar_arrive(uint32_t mbar) {
    asm volatile("mbarrier.arrive.shared.b64 _, [%0];" :: "r"(mbar) : "memory");
}
__device__ __forceinline__ void mbar_wait(uint32_t mbar, uint32_t parity) {
    uint32_t done;
    asm volatile(
        "{\n\t.reg .pred p;\n\t"
        "mbarrier.try_wait.parity.acquire.cta.shared::cta.b64 p, [%1], %2;\n\t"
        "selp.b32 %0, 1, 0, p;\n\t}"
        : "=r"(done) : "r"(mbar), "r"(parity) : "memory");
    if (!done) {
        asm volatile(
            "{\n\t.reg .pred P1;\n\t"
            "WL_%=:\n\t"
            "mbarrier.try_wait.parity.acquire.cta.shared::cta.b64 P1, [%0], %1, 0x989680;\n\t"
            "@P1 bra.uni WD_%=;\n\t"
            "bra.uni WL_%=;\n\t"
            "WD_%=:\n\t}"
            :: "r"(mbar), "r"(parity) : "memory");
    }
}
__device__ __forceinline__ void bulk_cp_row(uint32_t dst, const void* src, uint32_t mbar) {
    asm volatile(
        "cp.async.bulk.shared::cta.global.mbarrier::complete_tx::bytes [%0], [%1], %2, [%3];"
        :: "r"(dst), "l"(src), "r"((uint32_t)ROW_BYTES), "r"(mbar) : "memory");
}

// producer: stage tile `t` (global tile index within batch) into buffer `buf`
__device__ __forceinline__ void issue_tile(uint32_t sdyn_base, int buf,
                                           const float* pb, const float* gb,
                                           int t, uint32_t full_mbar) {
    const int px = t * TILE_PX;
    uint32_t dst = sdyn_base + buf * STAGE_BYTES;
    mbar_expect_tx(full_mbar, STAGE_BYTES);
    #pragma unroll
    for (int r = 0; r < 8; r++)
        bulk_cp_row(dst + r * ROW_BYTES, pb + r * HW + px, full_mbar);
    #pragma unroll
    for (int r = 0; r < 8; r++)
        bulk_cp_row(dst + (8 + r) * ROW_BYTES, gb + r * HW + px, full_mbar);
}

__global__ __launch_bounds__(TPB, 3)
void fused_kernel(const float* __restrict__ pred, const float* __restrict__ gt,
                  const int* __restrict__ num_objects, float* __restrict__ out) {
    extern __shared__ float sdyn[];
    __shared__ uint64_t mbars[2 * NSTAGE];   // full[0..1], empty[0..1]
    __shared__ float wsum[TPB / 32][NACC];
    __shared__ float a_sm[NACC];
    __shared__ float dice_sm[49];
    __shared__ float dp_sm[128];
    __shared__ int   flag_sm;

    // block -> (batch, chunk)
    int b, c, nck;
    if (blockIdx.x < 28 * 14) { b = blockIdx.x / 14; c = blockIdx.x % 14; nck = 14; }
    else { int r = blockIdx.x - 28 * 14; b = 28 + r / 13; c = r % 13; nck = 13; }

    const int t_lo = (c * TILES_PER_BATCH) / nck;
    const int t_hi = ((c + 1) * TILES_PER_BATCH) / nck;
    const int ntiles = t_hi - t_lo;

    const float* pb = pred + (size_t)b * NS * HW;
    const float* gb = gt   + (size_t)b * NS * HW;

    const uint32_t sdyn_base = (uint32_t)__cvta_generic_to_shared(sdyn);
    const uint32_t full0  = (uint32_t)__cvta_generic_to_shared(&mbars[0]);
    const uint32_t empty0 = (uint32_t)__cvta_generic_to_shared(&mbars[NSTAGE]);

    if (threadIdx.x == 0) {
        #pragma unroll
        for (int s = 0; s < NSTAGE; s++) {
            mbar_init(full0 + 8 * s, 1);        // completed by expect_tx bytes
            mbar_init(empty0 + 8 * s, TPB);     // all threads arrive per round
        }
    }
    __syncthreads();

    // prologue: fill both buffers (round 0, no empty-wait)
    if (threadIdx.x == 0) {
        issue_tile(sdyn_base, 0, pb, gb, t_lo + 0, full0 + 0);
        if (ntiles > 1) issue_tile(sdyn_base, 1, pb, gb, t_lo + 1, full0 + 8);
    }

    u64 inter2[49];
    u64 sp2[8], sg2[8], bg2 = 0ull;
    #pragma unroll
    for (int k = 0; k < 49; k++) inter2[k] = 0ull;
    #pragma unroll
    for (int s = 0; s < 8; s++) { sp2[s] = 0ull; sg2[s] = 0ull; }

    for (int i = 0; i < ntiles; i++) {
        const int buf = i & 1;
        const int r = i >> 1;
        mbar_wait(full0 + 8 * buf, r & 1);

        const u64* base = (const u64*)(sdyn + buf * STAGE_FLOATS);
        #pragma unroll
        for (int pass = 0; pass < 2; pass++) {
            const int col = threadIdx.x + pass * TPB;   // float2 col in [0,256)
            u64 p[8], g[8];
            #pragma unroll
            for (int s = 0; s < 8; s++) p[s] = base[s * (TILE_PX / 2) + col];
            #pragma unroll
            for (int s = 0; s < 8; s++) g[s] = base[(8 + s) * (TILE_PX / 2) + col];

            #pragma unroll
            for (int s = 0; s < 8; s++) sp2[s] = add2(sp2[s], p[s]);
            #pragma unroll
            for (int s = 0; s < 8; s++) sg2[s] = add2(sg2[s], g[s]);
            bg2 = ffma2(p[0], g[0], bg2);
            #pragma unroll
            for (int ii = 1; ii < 8; ii++)
                #pragma unroll
                for (int jj = 1; jj < 8; jj++)
                    inter2[(ii - 1) * 7 + (jj - 1)] =
                        ffma2(p[ii], g[jj], inter2[(ii - 1) * 7 + (jj - 1)]);
        }

        mbar_arrive(empty0 + 8 * buf);
        if (threadIdx.x == 0 && (i + 2) < ntiles) {
            // reuse buf for round r+1: wait round-r arrivals, then issue
            mbar_wait(empty0 + 8 * buf, r & 1);
            issue_tile(sdyn_base, buf, pb, gb, t_lo + i + 2, full0 + 8 * buf);
        }
    }

    // ---- block reduction -> g_part[b][c][*] ----
    const int wid = threadIdx.x >> 5;
    const int lane = threadIdx.x & 31;

    #pragma unroll
    for (int k = 0; k < 49; k++) {
        float2 t = unpack2(inter2[k]);
        float v = warp_sum(t.x + t.y);
        if (lane == 0) wsum[wid][k] = v;
    }
    #pragma unroll
    for (int s = 0; s < 8; s++) {
        float2 t = unpack2(sp2[s]);
        float v = warp_sum(t.x + t.y);
        if (lane == 0) wsum[wid][49 + s] = v;
    }
    #pragma unroll
    for (int s = 0; s < 8; s++) {
        float2 t = unpack2(sg2[s]);
        float v = warp_sum(t.x + t.y);
        if (lane == 0) wsum[wid][57 + s] = v;
    }
    {
        float2 t = unpack2(bg2);
        float v = warp_sum(t.x + t.y);
        if (lane == 0) wsum[wid][65] = v;
    }
    __syncthreads();
    if (threadIdx.x < NACC) {
        float v = 0.0f;
        #pragma unroll
        for (int w = 0; w < TPB / 32; w++) v += wsum[w][threadIdx.x];
        g_part[b][c][threadIdx.x] = v;
    }
    __threadfence();
    __syncthreads();

    // ---- last block of this batch runs the batch finalize ----
    if (threadIdx.x == 0) {
        int old = atomicAdd(&cnt_batch[b], 1);
        flag_sm = (old == nck - 1) ? 1 : 0;
    }
    __syncthreads();
    if (!flag_sm) return;
    __threadfence();   // acquire: see all chunks' g_part writes

    if (wid == 0) {
        int n = num_objects[b];
        if (n > 7) n = 7;
        if (n < 0) n = 0;

        for (int k = lane; k < NACC; k += 32) {
            float v = 0.0f;
            for (int cc = 0; cc < nck; cc++) v += g_part[b][cc][k];
            a_sm[k] = v;
        }
        __syncwarp();

        for (int idx = lane; idx < 49; idx += 32) {
            int p = idx / 7, g = idx % 7;
            dice_sm[idx] = (2.0f * a_sm[idx] + EPSF) /
                           (a_sm[50 + p] + a_sm[58 + g] + EPSF);
        }
        __syncwarp();

        // subset DP over pred-slot sets (exact optimal-assignment sum)
        #pragma unroll
        for (int q = 0; q < 4; q++) {
            int S = lane + 32 * q;
            dp_sm[S] = (S == 0) ? 0.0f : -1e30f;
        }
        __syncwarp();
        for (int k = 1; k <= n; k++) {
            float newv[4];
            #pragma unroll
            for (int q = 0; q < 4; q++) {
                int S = lane + 32 * q;
                float best = -1e30f;
                if (__popc(S) == k) {
                    #pragma unroll
                    for (int j = 0; j < 7; j++) {
                        if (S & (1 << j)) {
                            float cand = dp_sm[S & ~(1 << j)] + dice_sm[j * 7 + (k - 1)];
                            best = fmaxf(best, cand);
                        }
                    }
                }
                newv[q] = best;
            }
            __syncwarp();
            #pragma unroll
            for (int q = 0; q < 4; q++) {
                int S = lane + 32 * q;
                if (__popc(S) == k) dp_sm[S] = newv[q];
            }
            __syncwarp();
        }

        float best = -1e30f;
        #pragma unroll
        for (int q = 0; q < 4; q++) {
            int S = lane + 32 * q;
            if (__popc(S) == n) best = fmaxf(best, dp_sm[S]);
        }
        #pragma unroll
        for (int off = 16; off > 0; off >>= 1)
            best = fmaxf(best, __shfl_down_sync(0xffffffffu, best, off));

        if (lane == 0) {
            g_bg[b] = 1.0f - (2.0f * a_sm[65] + EPSF) /
                             (a_sm[49] + a_sm[57] + EPSF);
            g_fg[b] = (n > 0) ? ((float)n - best) : 0.0f;
            g_n[b]  = n;
            __threadfence();

            int gold = atomicAdd(&cnt_global, 1);
            if (gold == NB - 1) {
                __threadfence();
                float bg = 0.0f, fg = 0.0f;
                int cn = 0;
                #pragma unroll
                for (int bb = 0; bb < NB; bb++) {
                    bg += g_bg[bb];
                    fg += g_fg[bb];
                    cn += g_n[bb];
                }
                float bg_loss = bg / (float)NB;
                float fg_loss = (cn > 0) ? (fg / (float)cn) : 0.0f;
                out[0] = bg_loss + fg_loss;
                #pragma unroll
                for (int bb = 0; bb < NB; bb++) cnt_batch[bb] = 0;
                cnt_global = 0;
                __threadfence();
            }
        }
    }
}

extern "C" void kernel_launch(void* const* d_in, const int* in_sizes, int n_in,
                              void* d_out, int out_size) {
    const float* pred = (const float*)d_in[0];
    const float* gt   = (const float*)d_in[1];
    const int*   nobj = (const int*)d_in[2];
    float* out = (float*)d_out;

    cudaFuncSetAttribute(fused_kernel,
                         cudaFuncAttributeMaxDynamicSharedMemorySize, DYN_SMEM);
    fused_kernel<<<GRID_BLOCKS, TPB, DYN_SMEM>>>(pred, gt, nobj, out);
}